// round 13
// baseline (speedup 1.0000x reference)
#include <cuda_runtime.h>
#include <cuda_fp16.h>
#include <cuda_bf16.h>

#define NUM_LEVEL   16
#define TABLE_SIZE  (1u << 19)
#define TABLE_MASK  (TABLE_SIZE - 1u)
#define N_POINTS    262144
#define ENC_THREADS 256
#define MLP_THREADS 128
#define PTS_PER_WARP 16
#define STAGE_ST    20            // stage stride (floats): conflict-free frag loads

// 33.5 MB scratch for encoded features, [point][feat] fp32 (static __device__
// global — the sanctioned no-cudaMalloc workaround).
__device__ float g_enc[(size_t)N_POINTS * 32];

// Pre-split bf16 weights (hi/lo), [n][k] row-major, segments concatenated:
//   w_in  @     0  (64x32 = 2048)
//   w_h0  @  2048  (64x64 = 4096)
//   w_h1  @  6144  (64x64 = 4096)
//   w_out @ 10240  (16x64 = 1024)   total 11264 elems = 22.5 KB per array
__device__ __nv_bfloat16 g_whi[11264];
__device__ __nv_bfloat16 g_wlo[11264];
__device__ float         g_bias[208];   // b_in | b_h0 | b_h1 | b_out

// Resolutions: floor(16 * f32(32^(1/15))^l) computed in f32 as reference does.
__device__ __constant__ float c_res[NUM_LEVEL] = {
    16.f, 20.f, 25.f, 32.f, 40.f, 50.f, 64.f, 80.f,
    101.f, 128.f, 161.f, 203.f, 256.f, 322.f, 406.f, 512.f
};

// ---------------------------------------------------------------------------
// Prep kernel: one-shot fp32 -> split-bf16 weight conversion (2 us).
// Independent of encode output; runs before it on the same stream.
// ---------------------------------------------------------------------------
__global__ void prep_kernel(const float* __restrict__ w_in,
                            const float* __restrict__ w_h0,
                            const float* __restrict__ w_h1,
                            const float* __restrict__ w_out,
                            const float* __restrict__ b_in,
                            const float* __restrict__ b_h0,
                            const float* __restrict__ b_h1,
                            const float* __restrict__ b_out) {
    const int i = blockIdx.x * blockDim.x + threadIdx.x;
    float w = 0.f;
    bool valid = true;
    if      (i < 2048)  w = w_in[i];
    else if (i < 6144)  w = w_h0[i - 2048];
    else if (i < 10240) w = w_h1[i - 6144];
    else if (i < 11264) w = w_out[i - 10240];
    else valid = false;
    if (valid) {
        __nv_bfloat16 h = __float2bfloat16_rn(w);
        g_whi[i] = h;
        g_wlo[i] = __float2bfloat16_rn(w - __bfloat162float(h));
    }
    if (i < 64) {
        g_bias[i]       = b_in[i];
        g_bias[64 + i]  = b_h0[i];
        g_bias[128 + i] = b_h1[i];
    }
    if (i < 16) g_bias[192 + i] = b_out[i];
}

template <int SEL>
__device__ __forceinline__ float2 fetch_feat(const void* __restrict__ tables,
                                             int l, unsigned idx) {
    if (SEL == 0) {
        const __half2* t = (const __half2*)tables;
        return __half22float2(t[(size_t)l * TABLE_SIZE + idx]);
    } else if (SEL == 1) {
        const __nv_bfloat162* t = (const __nv_bfloat162*)tables;
        __nv_bfloat162 v = t[(size_t)l * TABLE_SIZE + idx];
        return make_float2(__bfloat162float(v.x), __bfloat162float(v.y));
    } else {
        const float2* t = (const float2*)tables;
        return t[(size_t)l * TABLE_SIZE + idx];
    }
}

// ---------------------------------------------------------------------------
// Kernel A: hash-grid encode only (unchanged from R10 best). Full grid +
// high occupancy; per-warp inline dtype detection.
// ---------------------------------------------------------------------------
template <int SEL>
__device__ __forceinline__ void encode_body(const float* __restrict__ coords,
                                            const void* __restrict__ tables,
                                            int p) {
    const float cx = coords[3 * p + 0];
    const float cy = coords[3 * p + 1];
    const float cz = coords[3 * p + 2];

    float4* dst = reinterpret_cast<float4*>(g_enc + (size_t)p * 32);
#pragma unroll 4
    for (int l = 0; l < NUM_LEVEL; l++) {
        const float res = c_res[l];
        const float sx = cx * res, sy = cy * res, sz = cz * res;
        const float fx = floorf(sx), fy = floorf(sy), fz = floorf(sz);
        const float gx = ceilf(sx),  gy = ceilf(sy),  gz = ceilf(sz);

        const unsigned hx0 = (unsigned)(int)fx;
        const unsigned hx1 = (unsigned)(int)gx;
        const unsigned hy0 = (unsigned)(int)fy * 2654435761u;
        const unsigned hy1 = (unsigned)(int)gy * 2654435761u;
        const unsigned hz0 = (unsigned)(int)fz * 805459861u;
        const unsigned hz1 = (unsigned)(int)gz * 805459861u;

        // ceil-s / s-floor kept literal so integer coords give exactly 0 weight
        const float wx0 = gx - sx, wx1 = sx - fx;
        const float wy0 = gy - sy, wy1 = sy - fy;
        const float wz0 = gz - sz, wz1 = sz - fz;

        float a0 = 0.f, a1 = 0.f;
#pragma unroll
        for (int o = 0; o < 8; o++) {
            const unsigned h = ((o & 4) ? hx1 : hx0)
                             ^ ((o & 2) ? hy1 : hy0)
                             ^ ((o & 1) ? hz1 : hz0);
            const float w = ((o & 4) ? wx1 : wx0)
                          * ((o & 2) ? wy1 : wy0)
                          * ((o & 1) ? wz1 : wz0);
            const float2 f = fetch_feat<SEL>(tables, l, h & TABLE_MASK);
            a0 = fmaf(f.x, w, a0);
            a1 = fmaf(f.y, w, a1);
        }
        if ((l & 1) == 0) {
            dst[l >> 1].x = a0; dst[l >> 1].y = a1;
        } else {
            float4 v = dst[l >> 1];          // compiler keeps in regs
            v.z = a0; v.w = a1;
            dst[l >> 1] = v;
        }
    }
}

__global__ void __launch_bounds__(ENC_THREADS, 4)
encode_kernel(const float* __restrict__ coords, const void* __restrict__ tables) {
    // Per-warp dtype detection (validated R9/R10: identical rel_err).
    const int lane = threadIdx.x & 31;
    const float vh = fabsf(__half2float(((const __half*)tables)[lane]));
    const float vb = fabsf(__bfloat162float(((const __nv_bfloat16*)tables)[lane]));
    const unsigned mh = __ballot_sync(0xFFFFFFFFu, vh >= 1e-6f && vh <= 2.5e-4f);
    const unsigned mb = __ballot_sync(0xFFFFFFFFu, vb >= 1e-6f && vb <= 2.5e-4f);
    const int sel = (__popc(mh) >= 24) ? 0 : ((__popc(mb) >= 24) ? 1 : 2);

    const int p = blockIdx.x * ENC_THREADS + threadIdx.x;
    if      (sel == 0) encode_body<0>(coords, tables, p);
    else if (sel == 1) encode_body<1>(coords, tables, p);
    else               encode_body<2>(coords, tables, p);
}

// ---------------------------------------------------------------------------
// Tensor-core MLP machinery, M=16 per warp (layouts = R6-validated, mt dropped)
// ---------------------------------------------------------------------------
__device__ __forceinline__ void mma_bf16(float c[4], const unsigned a[4],
                                         unsigned b0, unsigned b1) {
    asm("mma.sync.aligned.m16n8k16.row.col.f32.bf16.bf16.f32 "
        "{%0,%1,%2,%3}, {%4,%5,%6,%7}, {%8,%9}, {%0,%1,%2,%3};"
        : "+f"(c[0]), "+f"(c[1]), "+f"(c[2]), "+f"(c[3])
        : "r"(a[0]), "r"(a[1]), "r"(a[2]), "r"(a[3]), "r"(b0), "r"(b1));
}

__device__ __forceinline__ void split_pack(float x0, float x1,
                                           unsigned& hi, unsigned& lo) {
    __nv_bfloat162 h = __floats2bfloat162_rn(x0, x1);
    float r0 = x0 - __bfloat162float(h.x);
    float r1 = x1 - __bfloat162float(h.y);
    __nv_bfloat162 l = __floats2bfloat162_rn(r0, r1);
    hi = *reinterpret_cast<unsigned*>(&h);
    lo = *reinterpret_cast<unsigned*>(&l);
}

// One layer: acc[n][.] = bias + sum_k A[m,k] * W[n,k], split-bf16 3-pass.
// Weights from global (L1-resident, shared by all warps on the SM).
template <int KT, int NT>
__device__ __forceinline__ void gemm_layer(
    float (&acc)[8][4],
    const unsigned (&Ahi)[4][4], const unsigned (&Alo)[4][4],
    const __nv_bfloat16* __restrict__ whi, const __nv_bfloat16* __restrict__ wlo,
    const int K, const float* __restrict__ bias,
    const int l4, const int lm4)
{
#pragma unroll
    for (int nt = 0; nt < NT; nt++) {
        const float b0 = bias[nt * 8 + 2 * lm4];
        const float b1 = bias[nt * 8 + 2 * lm4 + 1];
        acc[nt][0] = b0; acc[nt][1] = b1;
        acc[nt][2] = b0; acc[nt][3] = b1;
    }
    const int k0 = 2 * lm4;
#pragma unroll
    for (int kt = 0; kt < KT; kt++) {
#pragma unroll
        for (int nt = 0; nt < NT; nt++) {
            const int j = nt * 8 + l4;
            const __nv_bfloat16* ph = whi + j * K + k0 + 16 * kt;
            const __nv_bfloat16* pl = wlo + j * K + k0 + 16 * kt;
            const unsigned bh0 = *reinterpret_cast<const unsigned*>(ph);
            const unsigned bh1 = *reinterpret_cast<const unsigned*>(ph + 8);
            const unsigned bl0 = *reinterpret_cast<const unsigned*>(pl);
            const unsigned bl1 = *reinterpret_cast<const unsigned*>(pl + 8);
            mma_bf16(acc[nt], Ahi[kt], bh0, bh1);
            mma_bf16(acc[nt], Ahi[kt], bl0, bl1);
            mma_bf16(acc[nt], Alo[kt], bh0, bh1);
        }
    }
}

// Accumulator (m16n8, n-tile pair 2u,2u+1) -> next-layer A frag (m16k16 tile u)
// after ReLU. Same validated mapping as R6, mt dimension removed.
__device__ __forceinline__ void build_frags(const float (&acc)[8][4],
                                            unsigned (&Ahi)[4][4],
                                            unsigned (&Alo)[4][4]) {
#pragma unroll
    for (int u = 0; u < 4; u++) {
        const float* a = acc[2 * u];
        const float* b = acc[2 * u + 1];
        split_pack(fmaxf(a[0], 0.f), fmaxf(a[1], 0.f), Ahi[u][0], Alo[u][0]);
        split_pack(fmaxf(a[2], 0.f), fmaxf(a[3], 0.f), Ahi[u][1], Alo[u][1]);
        split_pack(fmaxf(b[0], 0.f), fmaxf(b[1], 0.f), Ahi[u][2], Alo[u][2]);
        split_pack(fmaxf(b[2], 0.f), fmaxf(b[3], 0.f), Ahi[u][3], Alo[u][3]);
    }
}

// ---------------------------------------------------------------------------
// Kernel B: tensor-core MLP. 16 points/warp, weights via LDG (L1), enc via
// __ldcs streaming (evict-first, protects weight lines). No block barrier.
// ---------------------------------------------------------------------------
__global__ void __launch_bounds__(MLP_THREADS, 5)
mlp_kernel(float* __restrict__ out)
{
    __shared__ float stage[4][32 * STAGE_ST];   // 10240 B

    const int tid = threadIdx.x;
    const int lane = tid & 31, warp = tid >> 5;
    const int l4 = lane >> 2, lm4 = lane & 3;
    const int pbase = (blockIdx.x * 4 + warp) * PTS_PER_WARP;

    // ---- stage this warp's 16 points: lane -> (point = lane/2, half) ----
    float* st = stage[warp];
    {
        const int pt = lane >> 1, half = lane & 1;
        const float4* src = reinterpret_cast<const float4*>(
            g_enc + (size_t)(pbase + pt) * 32 + half * 16);
#pragma unroll
        for (int q = 0; q < 4; q++) {
            const float4 v = __ldcs(src + q);
            const int f = half * 16 + 4 * q;
            st[(f + 0) * STAGE_ST + pt] = v.x;
            st[(f + 1) * STAGE_ST + pt] = v.y;
            st[(f + 2) * STAGE_ST + pt] = v.z;
            st[(f + 3) * STAGE_ST + pt] = v.w;
        }
    }
    __syncwarp();

    // ---- layer-1 A frags (M=16 points, K=32 feats) ----
    unsigned Ahi[4][4], Alo[4][4];
#pragma unroll
    for (int kt = 0; kt < 2; kt++) {
        const int k0 = 2 * lm4 + 16 * kt;
        split_pack(st[k0 * STAGE_ST + l4],           st[(k0 + 1) * STAGE_ST + l4],
                   Ahi[kt][0], Alo[kt][0]);
        split_pack(st[k0 * STAGE_ST + l4 + 8],       st[(k0 + 1) * STAGE_ST + l4 + 8],
                   Ahi[kt][1], Alo[kt][1]);
        split_pack(st[(k0 + 8) * STAGE_ST + l4],     st[(k0 + 9) * STAGE_ST + l4],
                   Ahi[kt][2], Alo[kt][2]);
        split_pack(st[(k0 + 8) * STAGE_ST + l4 + 8], st[(k0 + 9) * STAGE_ST + l4 + 8],
                   Ahi[kt][3], Alo[kt][3]);
    }

    float acc[8][4];
    gemm_layer<2, 8>(acc, Ahi, Alo, g_whi,         g_wlo,         32, g_bias,       l4, lm4);
    build_frags(acc, Ahi, Alo);
    gemm_layer<4, 8>(acc, Ahi, Alo, g_whi + 2048,  g_wlo + 2048,  64, g_bias + 64,  l4, lm4);
    build_frags(acc, Ahi, Alo);
    gemm_layer<4, 8>(acc, Ahi, Alo, g_whi + 6144,  g_wlo + 6144,  64, g_bias + 128, l4, lm4);
    build_frags(acc, Ahi, Alo);
    gemm_layer<4, 2>(acc, Ahi, Alo, g_whi + 10240, g_wlo + 10240, 64, g_bias + 192, l4, lm4);

    // ---- store output (no activation on final layer) ----
    const int pr = pbase + l4;
#pragma unroll
    for (int nt = 0; nt < 2; nt++) {
        const int j = nt * 8 + 2 * lm4;
        *reinterpret_cast<float2*>(out + (size_t)pr * 16 + j) =
            make_float2(acc[nt][0], acc[nt][1]);
        *reinterpret_cast<float2*>(out + (size_t)(pr + 8) * 16 + j) =
            make_float2(acc[nt][2], acc[nt][3]);
    }
}

extern "C" void kernel_launch(void* const* d_in, const int* in_sizes, int n_in,
                              void* d_out, int out_size) {
    // Identify inputs BY ELEMENT COUNT (robust to metadata ordering).
    const float* coords = nullptr;
    const void*  tables = nullptr;
    const float* w_in = nullptr;  const float* w_h0 = nullptr;
    const float* w_h1 = nullptr;  const float* w_out = nullptr;
    const float* b64[3] = {nullptr, nullptr, nullptr};
    const float* b_out = nullptr;
    int n64 = 0, n4096 = 0;

    for (int i = 0; i < n_in; i++) {
        const int sz = in_sizes[i];
        const void* p = d_in[i];
        switch (sz) {
            case 786432:    coords = (const float*)p; break;     // 262144*3
            case 16777216:  tables = p;               break;     // 16*2^19*2
            case 2048:      w_in   = (const float*)p; break;     // 64*32
            case 1024:      w_out  = (const float*)p; break;     // 16*64
            case 4096:
                if (n4096 == 0) w_h0 = (const float*)p; else w_h1 = (const float*)p;
                n4096++; break;
            case 64:
                if (n64 < 3) b64[n64] = (const float*)p;
                n64++; break;
            case 16:        b_out  = (const float*)p; break;
            default: break;
        }
    }
    const float* b_in = b64[0];
    const float* b_h0 = b64[1];
    const float* b_h1 = b64[2];
    float* out = (float*)d_out;

    // Sequential full-grid launches on one stream (R9: chunking starves
    // encode occupancy; streams add risk for no measured gain).
    prep_kernel<<<44, 256>>>(w_in, w_h0, w_h1, w_out, b_in, b_h0, b_h1, b_out);
    encode_kernel<<<N_POINTS / ENC_THREADS, ENC_THREADS>>>(coords, tables);
    mlp_kernel<<<N_POINTS / (4 * PTS_PER_WARP), MLP_THREADS>>>(out);
}

// round 15
// speedup vs baseline: 1.5018x; 1.5018x over previous
#include <cuda_runtime.h>
#include <cuda_fp16.h>
#include <cuda_bf16.h>

#define NUM_LEVEL   16
#define TABLE_SIZE  (1u << 19)
#define TABLE_MASK  (TABLE_SIZE - 1u)
#define N_POINTS    262144
#define ENC_THREADS 256
#define MLP_THREADS 384                        // 12 warps = register-file limit
#define MLP_WARPS   (MLP_THREADS / 32)
#define PTS_PER_BLOCK (MLP_WARPS * 32)         // 384 points

// 33.5 MB scratch for encoded features, [point][feat] fp32 (static __device__
// global — the sanctioned no-cudaMalloc workaround).
__device__ float g_enc[(size_t)N_POINTS * 32];

// ---------------- MLP kernel shared-memory layout (dynamic, bytes) ---------
#define WSTRIDE_IN  40                         // 32 cols + 8 pad (bf16)
#define WSTRIDE_H   72                         // 64 cols + 8 pad
#define OFF_WHI_IN  0
#define SZ_W_IN     (64 * WSTRIDE_IN * 2)      // 5120
#define OFF_WLO_IN  (OFF_WHI_IN + SZ_W_IN)
#define OFF_WHI_H0  (OFF_WLO_IN + SZ_W_IN)
#define SZ_W_H      (64 * WSTRIDE_H * 2)       // 9216
#define OFF_WLO_H0  (OFF_WHI_H0 + SZ_W_H)
#define OFF_WHI_H1  (OFF_WLO_H0 + SZ_W_H)
#define OFF_WLO_H1  (OFF_WHI_H1 + SZ_W_H)
#define OFF_WHI_OUT (OFF_WLO_H1 + SZ_W_H)
#define SZ_W_OUT    (16 * WSTRIDE_H * 2)       // 2304
#define OFF_WLO_OUT (OFF_WHI_OUT + SZ_W_OUT)
#define OFF_BIAS    (OFF_WLO_OUT + SZ_W_OUT)   // 208 floats
#define OFF_STAGE   (OFF_BIAS + 208 * 4)
#define STAGE_PER_WARP (32 * 34 * 4)           // [feat][point] fp32, +2 pad
#define SMEM_TOTAL  (OFF_STAGE + MLP_WARPS * STAGE_PER_WARP)   // ~103.9 KB

// Resolutions: floor(16 * f32(32^(1/15))^l) computed in f32 as reference does.
__device__ __constant__ float c_res[NUM_LEVEL] = {
    16.f, 20.f, 25.f, 32.f, 40.f, 50.f, 64.f, 80.f,
    101.f, 128.f, 161.f, 203.f, 256.f, 322.f, 406.f, 512.f
};

template <int SEL>
__device__ __forceinline__ float2 fetch_feat(const void* __restrict__ tables,
                                             int l, unsigned idx) {
    if (SEL == 0) {
        const __half2* t = (const __half2*)tables;
        return __half22float2(t[(size_t)l * TABLE_SIZE + idx]);
    } else if (SEL == 1) {
        const __nv_bfloat162* t = (const __nv_bfloat162*)tables;
        __nv_bfloat162 v = t[(size_t)l * TABLE_SIZE + idx];
        return make_float2(__bfloat162float(v.x), __bfloat162float(v.y));
    } else {
        const float2* t = (const float2*)tables;
        return t[(size_t)l * TABLE_SIZE + idx];
    }
}

// ---------------------------------------------------------------------------
// Kernel A: hash-grid encode (unchanged R10 winner). Full grid + high
// occupancy; per-warp inline dtype detection.
// ---------------------------------------------------------------------------
template <int SEL>
__device__ __forceinline__ void encode_body(const float* __restrict__ coords,
                                            const void* __restrict__ tables,
                                            int p) {
    const float cx = coords[3 * p + 0];
    const float cy = coords[3 * p + 1];
    const float cz = coords[3 * p + 2];

    float4* dst = reinterpret_cast<float4*>(g_enc + (size_t)p * 32);
#pragma unroll 4
    for (int l = 0; l < NUM_LEVEL; l++) {
        const float res = c_res[l];
        const float sx = cx * res, sy = cy * res, sz = cz * res;
        const float fx = floorf(sx), fy = floorf(sy), fz = floorf(sz);
        const float gx = ceilf(sx),  gy = ceilf(sy),  gz = ceilf(sz);

        const unsigned hx0 = (unsigned)(int)fx;
        const unsigned hx1 = (unsigned)(int)gx;
        const unsigned hy0 = (unsigned)(int)fy * 2654435761u;
        const unsigned hy1 = (unsigned)(int)gy * 2654435761u;
        const unsigned hz0 = (unsigned)(int)fz * 805459861u;
        const unsigned hz1 = (unsigned)(int)gz * 805459861u;

        // ceil-s / s-floor kept literal so integer coords give exactly 0 weight
        const float wx0 = gx - sx, wx1 = sx - fx;
        const float wy0 = gy - sy, wy1 = sy - fy;
        const float wz0 = gz - sz, wz1 = sz - fz;

        float a0 = 0.f, a1 = 0.f;
#pragma unroll
        for (int o = 0; o < 8; o++) {
            const unsigned h = ((o & 4) ? hx1 : hx0)
                             ^ ((o & 2) ? hy1 : hy0)
                             ^ ((o & 1) ? hz1 : hz0);
            const float w = ((o & 4) ? wx1 : wx0)
                          * ((o & 2) ? wy1 : wy0)
                          * ((o & 1) ? wz1 : wz0);
            const float2 f = fetch_feat<SEL>(tables, l, h & TABLE_MASK);
            a0 = fmaf(f.x, w, a0);
            a1 = fmaf(f.y, w, a1);
        }
        if ((l & 1) == 0) {
            dst[l >> 1].x = a0; dst[l >> 1].y = a1;
        } else {
            float4 v = dst[l >> 1];          // compiler keeps in regs
            v.z = a0; v.w = a1;
            dst[l >> 1] = v;
        }
    }
}

__global__ void __launch_bounds__(ENC_THREADS, 4)
encode_kernel(const float* __restrict__ coords, const void* __restrict__ tables) {
    // Per-warp dtype detection (validated R9/R10: identical rel_err).
    const int lane = threadIdx.x & 31;
    const float vh = fabsf(__half2float(((const __half*)tables)[lane]));
    const float vb = fabsf(__bfloat162float(((const __nv_bfloat16*)tables)[lane]));
    const unsigned mh = __ballot_sync(0xFFFFFFFFu, vh >= 1e-6f && vh <= 2.5e-4f);
    const unsigned mb = __ballot_sync(0xFFFFFFFFu, vb >= 1e-6f && vb <= 2.5e-4f);
    const int sel = (__popc(mh) >= 24) ? 0 : ((__popc(mb) >= 24) ? 1 : 2);

    const int p = blockIdx.x * ENC_THREADS + threadIdx.x;
    if      (sel == 0) encode_body<0>(coords, tables, p);
    else if (sel == 1) encode_body<1>(coords, tables, p);
    else               encode_body<2>(coords, tables, p);
}

// ---------------------------------------------------------------------------
// Tensor-core MLP machinery (R6/R10-validated, M=32 per warp, smem weights)
// ---------------------------------------------------------------------------
__device__ __forceinline__ void mma_bf16(float c[4], const unsigned a[4],
                                         unsigned b0, unsigned b1) {
    asm("mma.sync.aligned.m16n8k16.row.col.f32.bf16.bf16.f32 "
        "{%0,%1,%2,%3}, {%4,%5,%6,%7}, {%8,%9}, {%0,%1,%2,%3};"
        : "+f"(c[0]), "+f"(c[1]), "+f"(c[2]), "+f"(c[3])
        : "r"(a[0]), "r"(a[1]), "r"(a[2]), "r"(a[3]), "r"(b0), "r"(b1));
}

__device__ __forceinline__ void split_pack(float x0, float x1,
                                           unsigned& hi, unsigned& lo) {
    __nv_bfloat162 h = __floats2bfloat162_rn(x0, x1);
    float r0 = x0 - __bfloat162float(h.x);
    float r1 = x1 - __bfloat162float(h.y);
    __nv_bfloat162 l = __floats2bfloat162_rn(r0, r1);
    hi = *reinterpret_cast<unsigned*>(&h);
    lo = *reinterpret_cast<unsigned*>(&l);
}

template <int KT, int NT>
__device__ __forceinline__ void gemm_layer(
    float (&acc)[2][8][4],
    const unsigned (&Ahi)[4][2][4], const unsigned (&Alo)[4][2][4],
    const __nv_bfloat16* __restrict__ whi, const __nv_bfloat16* __restrict__ wlo,
    const int wstride, const float* __restrict__ bias,
    const int l4, const int lm4)
{
#pragma unroll
    for (int nt = 0; nt < NT; nt++) {
        const float b0 = bias[nt * 8 + 2 * lm4];
        const float b1 = bias[nt * 8 + 2 * lm4 + 1];
#pragma unroll
        for (int mt = 0; mt < 2; mt++) {
            acc[mt][nt][0] = b0; acc[mt][nt][1] = b1;
            acc[mt][nt][2] = b0; acc[mt][nt][3] = b1;
        }
    }
    const int k0 = 2 * lm4;
#pragma unroll
    for (int kt = 0; kt < KT; kt++) {
#pragma unroll
        for (int nt = 0; nt < NT; nt++) {
            const int j = nt * 8 + l4;
            const __nv_bfloat16* ph = whi + j * wstride + k0 + 16 * kt;
            const __nv_bfloat16* pl = wlo + j * wstride + k0 + 16 * kt;
            const unsigned bh0 = *reinterpret_cast<const unsigned*>(ph);
            const unsigned bh1 = *reinterpret_cast<const unsigned*>(ph + 8);
            const unsigned bl0 = *reinterpret_cast<const unsigned*>(pl);
            const unsigned bl1 = *reinterpret_cast<const unsigned*>(pl + 8);
#pragma unroll
            for (int mt = 0; mt < 2; mt++) {
                mma_bf16(acc[mt][nt], Ahi[kt][mt], bh0, bh1);
                mma_bf16(acc[mt][nt], Ahi[kt][mt], bl0, bl1);
                mma_bf16(acc[mt][nt], Alo[kt][mt], bh0, bh1);
            }
        }
    }
}

__device__ __forceinline__ void build_frags64(const float (&acc)[2][8][4],
                                              unsigned (&Ahi)[4][2][4],
                                              unsigned (&Alo)[4][2][4]) {
#pragma unroll
    for (int u = 0; u < 4; u++)
#pragma unroll
        for (int mt = 0; mt < 2; mt++) {
            const float* a = acc[mt][2 * u];
            const float* b = acc[mt][2 * u + 1];
            split_pack(fmaxf(a[0], 0.f), fmaxf(a[1], 0.f), Ahi[u][mt][0], Alo[u][mt][0]);
            split_pack(fmaxf(a[2], 0.f), fmaxf(a[3], 0.f), Ahi[u][mt][1], Alo[u][mt][1]);
            split_pack(fmaxf(b[0], 0.f), fmaxf(b[1], 0.f), Ahi[u][mt][2], Alo[u][mt][2]);
            split_pack(fmaxf(b[2], 0.f), fmaxf(b[3], 0.f), Ahi[u][mt][3], Alo[u][mt][3]);
        }
}

// ---------------------------------------------------------------------------
// Kernel B: tensor-core MLP. 384 threads (12 warps = reg-file limit) share
// ONE smem weight copy -> 12 warps/SM (vs 8 in the 128-thread shape) and
// weight prep amortized over 384 points.
// ---------------------------------------------------------------------------
__global__ void __launch_bounds__(MLP_THREADS)
mlp_kernel(const float* __restrict__ w_in,  const float* __restrict__ b_in,
           const float* __restrict__ w_h0,  const float* __restrict__ b_h0,
           const float* __restrict__ w_h1,  const float* __restrict__ b_h1,
           const float* __restrict__ w_out, const float* __restrict__ b_out,
           float* __restrict__ out)
{
    extern __shared__ char smem[];
    __nv_bfloat16* s_whi_in  = (__nv_bfloat16*)(smem + OFF_WHI_IN);
    __nv_bfloat16* s_wlo_in  = (__nv_bfloat16*)(smem + OFF_WLO_IN);
    __nv_bfloat16* s_whi_h0  = (__nv_bfloat16*)(smem + OFF_WHI_H0);
    __nv_bfloat16* s_wlo_h0  = (__nv_bfloat16*)(smem + OFF_WLO_H0);
    __nv_bfloat16* s_whi_h1  = (__nv_bfloat16*)(smem + OFF_WHI_H1);
    __nv_bfloat16* s_wlo_h1  = (__nv_bfloat16*)(smem + OFF_WLO_H1);
    __nv_bfloat16* s_whi_out = (__nv_bfloat16*)(smem + OFF_WHI_OUT);
    __nv_bfloat16* s_wlo_out = (__nv_bfloat16*)(smem + OFF_WLO_OUT);
    float*         s_bias    = (float*)(smem + OFF_BIAS);

    const int tid = threadIdx.x;

    // ---- weight prep: fp32 -> (bf16 hi, bf16 lo), padded rows ----
    for (int i = tid; i < 64 * 32; i += MLP_THREADS) {
        float w = w_in[i];
        __nv_bfloat16 h = __float2bfloat16_rn(w);
        __nv_bfloat16 l = __float2bfloat16_rn(w - __bfloat162float(h));
        int idx = (i >> 5) * WSTRIDE_IN + (i & 31);
        s_whi_in[idx] = h; s_wlo_in[idx] = l;
    }
    for (int i = tid; i < 64 * 64; i += MLP_THREADS) {
        int idx = (i >> 6) * WSTRIDE_H + (i & 63);
        float w0 = w_h0[i];
        __nv_bfloat16 h0 = __float2bfloat16_rn(w0);
        s_whi_h0[idx] = h0;
        s_wlo_h0[idx] = __float2bfloat16_rn(w0 - __bfloat162float(h0));
        float w1 = w_h1[i];
        __nv_bfloat16 h1 = __float2bfloat16_rn(w1);
        s_whi_h1[idx] = h1;
        s_wlo_h1[idx] = __float2bfloat16_rn(w1 - __bfloat162float(h1));
    }
    for (int i = tid; i < 16 * 64; i += MLP_THREADS) {
        float w = w_out[i];
        __nv_bfloat16 h = __float2bfloat16_rn(w);
        int idx = (i >> 6) * WSTRIDE_H + (i & 63);
        s_whi_out[idx] = h;
        s_wlo_out[idx] = __float2bfloat16_rn(w - __bfloat162float(h));
    }
    if (tid < 64) {
        s_bias[tid]       = b_in[tid];
        s_bias[64 + tid]  = b_h0[tid];
        s_bias[128 + tid] = b_h1[tid];
    }
    if (tid < 16) s_bias[192 + tid] = b_out[tid];
    __syncthreads();

    // ---- warp-uniform tail guard (after the block barrier) ----
    const int lane = tid & 31, warp = tid >> 5;
    const int pbase = blockIdx.x * PTS_PER_BLOCK + warp * 32;
    if (pbase >= N_POINTS) return;

    // ---- load enc for this warp's 32 points (coalesced 128B) into stage ----
    const int p = pbase + lane;
    const int l4 = lane >> 2, lm4 = lane & 3;
    float* st = (float*)(smem + OFF_STAGE + warp * STAGE_PER_WARP);
    const float4* src = reinterpret_cast<const float4*>(g_enc + (size_t)p * 32);
#pragma unroll
    for (int q = 0; q < 8; q++) {
        const float4 v = src[q];
        st[(4 * q + 0) * 34 + lane] = v.x;
        st[(4 * q + 1) * 34 + lane] = v.y;
        st[(4 * q + 2) * 34 + lane] = v.z;
        st[(4 * q + 3) * 34 + lane] = v.w;
    }
    __syncwarp();

    // ---- layer-1 A frags (M=32 points, K=32 feats) ----
    unsigned Ahi[4][2][4], Alo[4][2][4];
#pragma unroll
    for (int kt = 0; kt < 2; kt++)
#pragma unroll
        for (int mt = 0; mt < 2; mt++) {
            const int r  = l4 + 16 * mt;
            const int k0 = 2 * lm4 + 16 * kt;
            float e00 = st[k0 * 34 + r],           e01 = st[(k0 + 1) * 34 + r];
            float e10 = st[k0 * 34 + r + 8],       e11 = st[(k0 + 1) * 34 + r + 8];
            float e20 = st[(k0 + 8) * 34 + r],     e21 = st[(k0 + 9) * 34 + r];
            float e30 = st[(k0 + 8) * 34 + r + 8], e31 = st[(k0 + 9) * 34 + r + 8];
            split_pack(e00, e01, Ahi[kt][mt][0], Alo[kt][mt][0]);
            split_pack(e10, e11, Ahi[kt][mt][1], Alo[kt][mt][1]);
            split_pack(e20, e21, Ahi[kt][mt][2], Alo[kt][mt][2]);
            split_pack(e30, e31, Ahi[kt][mt][3], Alo[kt][mt][3]);
        }

    float acc[2][8][4];
    gemm_layer<2, 8>(acc, Ahi, Alo, s_whi_in,  s_wlo_in,  WSTRIDE_IN, s_bias,       l4, lm4);
    build_frags64(acc, Ahi, Alo);
    gemm_layer<4, 8>(acc, Ahi, Alo, s_whi_h0,  s_wlo_h0,  WSTRIDE_H,  s_bias + 64,  l4, lm4);
    build_frags64(acc, Ahi, Alo);
    gemm_layer<4, 8>(acc, Ahi, Alo, s_whi_h1,  s_wlo_h1,  WSTRIDE_H,  s_bias + 128, l4, lm4);
    build_frags64(acc, Ahi, Alo);
    gemm_layer<4, 2>(acc, Ahi, Alo, s_whi_out, s_wlo_out, WSTRIDE_H,  s_bias + 192, l4, lm4);

    // ---- store output (no activation on final layer) ----
#pragma unroll
    for (int mt = 0; mt < 2; mt++)
#pragma unroll
        for (int nt = 0; nt < 2; nt++) {
            const int j  = nt * 8 + 2 * lm4;
            const int pr = pbase + l4 + 16 * mt;
            *reinterpret_cast<float2*>(out + (size_t)pr * 16 + j) =
                make_float2(acc[mt][nt][0], acc[mt][nt][1]);
            *reinterpret_cast<float2*>(out + (size_t)(pr + 8) * 16 + j) =
                make_float2(acc[mt][nt][2], acc[mt][nt][3]);
        }
}

extern "C" void kernel_launch(void* const* d_in, const int* in_sizes, int n_in,
                              void* d_out, int out_size) {
    // Identify inputs BY ELEMENT COUNT (robust to metadata ordering).
    const float* coords = nullptr;
    const void*  tables = nullptr;
    const float* w_in = nullptr;  const float* w_h0 = nullptr;
    const float* w_h1 = nullptr;  const float* w_out = nullptr;
    const float* b64[3] = {nullptr, nullptr, nullptr};
    const float* b_out = nullptr;
    int n64 = 0, n4096 = 0;

    for (int i = 0; i < n_in; i++) {
        const int sz = in_sizes[i];
        const void* p = d_in[i];
        switch (sz) {
            case 786432:    coords = (const float*)p; break;     // 262144*3
            case 16777216:  tables = p;               break;     // 16*2^19*2
            case 2048:      w_in   = (const float*)p; break;     // 64*32
            case 1024:      w_out  = (const float*)p; break;     // 16*64
            case 4096:
                if (n4096 == 0) w_h0 = (const float*)p; else w_h1 = (const float*)p;
                n4096++; break;
            case 64:
                if (n64 < 3) b64[n64] = (const float*)p;
                n64++; break;
            case 16:        b_out  = (const float*)p; break;
            default: break;
        }
    }
    const float* b_in = b64[0];
    const float* b_h0 = b64[1];
    const float* b_h1 = b64[2];
    float* out = (float*)d_out;

    static bool attr_set = false;
    if (!attr_set) {
        cudaFuncSetAttribute(mlp_kernel,
                             cudaFuncAttributeMaxDynamicSharedMemorySize,
                             SMEM_TOTAL);
        attr_set = true;
    }

    // Sequential, full-grid launches (R9: chunking starves encode occupancy;
    // R13: LDG weights starve the LSU — weights stay in smem).
    encode_kernel<<<N_POINTS / ENC_THREADS, ENC_THREADS>>>(coords, tables);
    const int mlp_grid = (N_POINTS + PTS_PER_BLOCK - 1) / PTS_PER_BLOCK;  // 683
    mlp_kernel<<<mlp_grid, MLP_THREADS, SMEM_TOTAL>>>(
        w_in, b_in, w_h0, b_h0, w_h1, b_h1, w_out, b_out, out);
}

// round 16
// speedup vs baseline: 1.5742x; 1.0482x over previous
#include <cuda_runtime.h>
#include <cuda_fp16.h>
#include <cuda_bf16.h>

#define NUM_LEVEL   16
#define TABLE_SIZE  (1u << 19)
#define TABLE_MASK  (TABLE_SIZE - 1u)
#define N_POINTS    262144
#define ENC_THREADS 256
#define MLP_THREADS 512                        // 16 warps, one weight copy
#define MLP_WARPS   (MLP_THREADS / 32)
#define PTS_PER_WARP 16                        // M=16 per warp (fewer regs)
#define PTS_PER_BLOCK (MLP_WARPS * PTS_PER_WARP)   // 256

// 33.5 MB scratch for encoded features, [point][feat] fp32 (static __device__
// global — the sanctioned no-cudaMalloc workaround).
__device__ float g_enc[(size_t)N_POINTS * 32];

// ---------------- MLP kernel shared-memory layout (dynamic, bytes) ---------
#define WSTRIDE_IN  40                         // 32 cols + 8 pad (bf16)
#define WSTRIDE_H   72                         // 64 cols + 8 pad
#define OFF_WHI_IN  0
#define SZ_W_IN     (64 * WSTRIDE_IN * 2)      // 5120
#define OFF_WLO_IN  (OFF_WHI_IN + SZ_W_IN)
#define OFF_WHI_H0  (OFF_WLO_IN + SZ_W_IN)
#define SZ_W_H      (64 * WSTRIDE_H * 2)       // 9216
#define OFF_WLO_H0  (OFF_WHI_H0 + SZ_W_H)
#define OFF_WHI_H1  (OFF_WLO_H0 + SZ_W_H)
#define OFF_WLO_H1  (OFF_WHI_H1 + SZ_W_H)
#define OFF_WHI_OUT (OFF_WLO_H1 + SZ_W_H)
#define SZ_W_OUT    (16 * WSTRIDE_H * 2)       // 2304
#define OFF_WLO_OUT (OFF_WHI_OUT + SZ_W_OUT)
#define OFF_BIAS    (OFF_WLO_OUT + SZ_W_OUT)   // 208 floats
#define OFF_STAGE   (OFF_BIAS + 208 * 4)
#define STAGE_ST    18                         // 16 points + 2 pad
#define STAGE_PER_WARP (32 * STAGE_ST * 4)     // 2304 B
#define SMEM_TOTAL  (OFF_STAGE + MLP_WARPS * STAGE_PER_WARP)   // ~87.5 KB

// Resolutions: floor(16 * f32(32^(1/15))^l) computed in f32 as reference does.
__device__ __constant__ float c_res[NUM_LEVEL] = {
    16.f, 20.f, 25.f, 32.f, 40.f, 50.f, 64.f, 80.f,
    101.f, 128.f, 161.f, 203.f, 256.f, 322.f, 406.f, 512.f
};

template <int SEL>
__device__ __forceinline__ float2 fetch_feat(const void* __restrict__ tables,
                                             int l, unsigned idx) {
    if (SEL == 0) {
        const __half2* t = (const __half2*)tables;
        return __half22float2(t[(size_t)l * TABLE_SIZE + idx]);
    } else if (SEL == 1) {
        const __nv_bfloat162* t = (const __nv_bfloat162*)tables;
        __nv_bfloat162 v = t[(size_t)l * TABLE_SIZE + idx];
        return make_float2(__bfloat162float(v.x), __bfloat162float(v.y));
    } else {
        const float2* t = (const float2*)tables;
        return t[(size_t)l * TABLE_SIZE + idx];
    }
}

// ---------------------------------------------------------------------------
// Kernel A: hash-grid encode (unchanged R10 winner).
// ---------------------------------------------------------------------------
template <int SEL>
__device__ __forceinline__ void encode_body(const float* __restrict__ coords,
                                            const void* __restrict__ tables,
                                            int p) {
    const float cx = coords[3 * p + 0];
    const float cy = coords[3 * p + 1];
    const float cz = coords[3 * p + 2];

    float4* dst = reinterpret_cast<float4*>(g_enc + (size_t)p * 32);
#pragma unroll 4
    for (int l = 0; l < NUM_LEVEL; l++) {
        const float res = c_res[l];
        const float sx = cx * res, sy = cy * res, sz = cz * res;
        const float fx = floorf(sx), fy = floorf(sy), fz = floorf(sz);
        const float gx = ceilf(sx),  gy = ceilf(sy),  gz = ceilf(sz);

        const unsigned hx0 = (unsigned)(int)fx;
        const unsigned hx1 = (unsigned)(int)gx;
        const unsigned hy0 = (unsigned)(int)fy * 2654435761u;
        const unsigned hy1 = (unsigned)(int)gy * 2654435761u;
        const unsigned hz0 = (unsigned)(int)fz * 805459861u;
        const unsigned hz1 = (unsigned)(int)gz * 805459861u;

        // ceil-s / s-floor kept literal so integer coords give exactly 0 weight
        const float wx0 = gx - sx, wx1 = sx - fx;
        const float wy0 = gy - sy, wy1 = sy - fy;
        const float wz0 = gz - sz, wz1 = sz - fz;

        float a0 = 0.f, a1 = 0.f;
#pragma unroll
        for (int o = 0; o < 8; o++) {
            const unsigned h = ((o & 4) ? hx1 : hx0)
                             ^ ((o & 2) ? hy1 : hy0)
                             ^ ((o & 1) ? hz1 : hz0);
            const float w = ((o & 4) ? wx1 : wx0)
                          * ((o & 2) ? wy1 : wy0)
                          * ((o & 1) ? wz1 : wz0);
            const float2 f = fetch_feat<SEL>(tables, l, h & TABLE_MASK);
            a0 = fmaf(f.x, w, a0);
            a1 = fmaf(f.y, w, a1);
        }
        if ((l & 1) == 0) {
            dst[l >> 1].x = a0; dst[l >> 1].y = a1;
        } else {
            float4 v = dst[l >> 1];          // compiler keeps in regs
            v.z = a0; v.w = a1;
            dst[l >> 1] = v;
        }
    }
}

__global__ void __launch_bounds__(ENC_THREADS, 4)
encode_kernel(const float* __restrict__ coords, const void* __restrict__ tables) {
    // Per-warp dtype detection (validated R9/R10: identical rel_err).
    const int lane = threadIdx.x & 31;
    const float vh = fabsf(__half2float(((const __half*)tables)[lane]));
    const float vb = fabsf(__bfloat162float(((const __nv_bfloat16*)tables)[lane]));
    const unsigned mh = __ballot_sync(0xFFFFFFFFu, vh >= 1e-6f && vh <= 2.5e-4f);
    const unsigned mb = __ballot_sync(0xFFFFFFFFu, vb >= 1e-6f && vb <= 2.5e-4f);
    const int sel = (__popc(mh) >= 24) ? 0 : ((__popc(mb) >= 24) ? 1 : 2);

    const int p = blockIdx.x * ENC_THREADS + threadIdx.x;
    if      (sel == 0) encode_body<0>(coords, tables, p);
    else if (sel == 1) encode_body<1>(coords, tables, p);
    else               encode_body<2>(coords, tables, p);
}

// ---------------------------------------------------------------------------
// Tensor-core MLP machinery — M=16 per warp (R6 layouts, mt dimension removed)
// ---------------------------------------------------------------------------
__device__ __forceinline__ void mma_bf16(float c[4], const unsigned a[4],
                                         unsigned b0, unsigned b1) {
    asm("mma.sync.aligned.m16n8k16.row.col.f32.bf16.bf16.f32 "
        "{%0,%1,%2,%3}, {%4,%5,%6,%7}, {%8,%9}, {%0,%1,%2,%3};"
        : "+f"(c[0]), "+f"(c[1]), "+f"(c[2]), "+f"(c[3])
        : "r"(a[0]), "r"(a[1]), "r"(a[2]), "r"(a[3]), "r"(b0), "r"(b1));
}

__device__ __forceinline__ void split_pack(float x0, float x1,
                                           unsigned& hi, unsigned& lo) {
    __nv_bfloat162 h = __floats2bfloat162_rn(x0, x1);
    float r0 = x0 - __bfloat162float(h.x);
    float r1 = x1 - __bfloat162float(h.y);
    __nv_bfloat162 l = __floats2bfloat162_rn(r0, r1);
    hi = *reinterpret_cast<unsigned*>(&h);
    lo = *reinterpret_cast<unsigned*>(&l);
}

template <int KT, int NT>
__device__ __forceinline__ void gemm_layer(
    float (&acc)[8][4],
    const unsigned (&Ahi)[4][4], const unsigned (&Alo)[4][4],
    const __nv_bfloat16* __restrict__ whi, const __nv_bfloat16* __restrict__ wlo,
    const int wstride, const float* __restrict__ bias,
    const int l4, const int lm4)
{
#pragma unroll
    for (int nt = 0; nt < NT; nt++) {
        const float b0 = bias[nt * 8 + 2 * lm4];
        const float b1 = bias[nt * 8 + 2 * lm4 + 1];
        acc[nt][0] = b0; acc[nt][1] = b1;
        acc[nt][2] = b0; acc[nt][3] = b1;
    }
    const int k0 = 2 * lm4;
#pragma unroll
    for (int kt = 0; kt < KT; kt++) {
#pragma unroll
        for (int nt = 0; nt < NT; nt++) {
            const int j = nt * 8 + l4;
            const __nv_bfloat16* ph = whi + j * wstride + k0 + 16 * kt;
            const __nv_bfloat16* pl = wlo + j * wstride + k0 + 16 * kt;
            const unsigned bh0 = *reinterpret_cast<const unsigned*>(ph);
            const unsigned bh1 = *reinterpret_cast<const unsigned*>(ph + 8);
            const unsigned bl0 = *reinterpret_cast<const unsigned*>(pl);
            const unsigned bl1 = *reinterpret_cast<const unsigned*>(pl + 8);
            mma_bf16(acc[nt], Ahi[kt], bh0, bh1);
            mma_bf16(acc[nt], Ahi[kt], bl0, bl1);
            mma_bf16(acc[nt], Alo[kt], bh0, bh1);
        }
    }
}

// Accumulator (m16n8, n-tile pair 2u,2u+1) -> next-layer A frag (m16k16 tile u)
// after ReLU. R6-validated mapping, mt removed.
__device__ __forceinline__ void build_frags(const float (&acc)[8][4],
                                            unsigned (&Ahi)[4][4],
                                            unsigned (&Alo)[4][4]) {
#pragma unroll
    for (int u = 0; u < 4; u++) {
        const float* a = acc[2 * u];
        const float* b = acc[2 * u + 1];
        split_pack(fmaxf(a[0], 0.f), fmaxf(a[1], 0.f), Ahi[u][0], Alo[u][0]);
        split_pack(fmaxf(a[2], 0.f), fmaxf(a[3], 0.f), Ahi[u][1], Alo[u][1]);
        split_pack(fmaxf(b[0], 0.f), fmaxf(b[1], 0.f), Ahi[u][2], Alo[u][2]);
        split_pack(fmaxf(b[2], 0.f), fmaxf(b[3], 0.f), Ahi[u][3], Alo[u][3]);
    }
}

// ---------------------------------------------------------------------------
// Kernel B: tensor-core MLP. 512 threads (16 warps) share ONE smem weight
// copy; M=16/warp halves frag+acc registers -> 16 warps/SM (4 per SMSP).
// ---------------------------------------------------------------------------
__global__ void __launch_bounds__(MLP_THREADS)
mlp_kernel(const float* __restrict__ w_in,  const float* __restrict__ b_in,
           const float* __restrict__ w_h0,  const float* __restrict__ b_h0,
           const float* __restrict__ w_h1,  const float* __restrict__ b_h1,
           const float* __restrict__ w_out, const float* __restrict__ b_out,
           float* __restrict__ out)
{
    extern __shared__ char smem[];
    __nv_bfloat16* s_whi_in  = (__nv_bfloat16*)(smem + OFF_WHI_IN);
    __nv_bfloat16* s_wlo_in  = (__nv_bfloat16*)(smem + OFF_WLO_IN);
    __nv_bfloat16* s_whi_h0  = (__nv_bfloat16*)(smem + OFF_WHI_H0);
    __nv_bfloat16* s_wlo_h0  = (__nv_bfloat16*)(smem + OFF_WLO_H0);
    __nv_bfloat16* s_whi_h1  = (__nv_bfloat16*)(smem + OFF_WHI_H1);
    __nv_bfloat16* s_wlo_h1  = (__nv_bfloat16*)(smem + OFF_WLO_H1);
    __nv_bfloat16* s_whi_out = (__nv_bfloat16*)(smem + OFF_WHI_OUT);
    __nv_bfloat16* s_wlo_out = (__nv_bfloat16*)(smem + OFF_WLO_OUT);
    float*         s_bias    = (float*)(smem + OFF_BIAS);

    const int tid = threadIdx.x;

    // ---- weight prep: fp32 -> (bf16 hi, bf16 lo), padded rows ----
    for (int i = tid; i < 64 * 32; i += MLP_THREADS) {
        float w = w_in[i];
        __nv_bfloat16 h = __float2bfloat16_rn(w);
        __nv_bfloat16 l = __float2bfloat16_rn(w - __bfloat162float(h));
        int idx = (i >> 5) * WSTRIDE_IN + (i & 31);
        s_whi_in[idx] = h; s_wlo_in[idx] = l;
    }
    for (int i = tid; i < 64 * 64; i += MLP_THREADS) {
        int idx = (i >> 6) * WSTRIDE_H + (i & 63);
        float w0 = w_h0[i];
        __nv_bfloat16 h0 = __float2bfloat16_rn(w0);
        s_whi_h0[idx] = h0;
        s_wlo_h0[idx] = __float2bfloat16_rn(w0 - __bfloat162float(h0));
        float w1 = w_h1[i];
        __nv_bfloat16 h1 = __float2bfloat16_rn(w1);
        s_whi_h1[idx] = h1;
        s_wlo_h1[idx] = __float2bfloat16_rn(w1 - __bfloat162float(h1));
    }
    for (int i = tid; i < 16 * 64; i += MLP_THREADS) {
        float w = w_out[i];
        __nv_bfloat16 h = __float2bfloat16_rn(w);
        int idx = (i >> 6) * WSTRIDE_H + (i & 63);
        s_whi_out[idx] = h;
        s_wlo_out[idx] = __float2bfloat16_rn(w - __bfloat162float(h));
    }
    if (tid < 64) {
        s_bias[tid]       = b_in[tid];
        s_bias[64 + tid]  = b_h0[tid];
        s_bias[128 + tid] = b_h1[tid];
    }
    if (tid < 16) s_bias[192 + tid] = b_out[tid];
    __syncthreads();

    const int lane = tid & 31, warp = tid >> 5;
    const int l4 = lane >> 2, lm4 = lane & 3;
    const int pbase = blockIdx.x * PTS_PER_BLOCK + warp * PTS_PER_WARP;

    // ---- stage this warp's 16 points: lane -> (point = lane/2, half) ----
    float* st = (float*)(smem + OFF_STAGE + warp * STAGE_PER_WARP);
    {
        const int pt = lane >> 1, half = lane & 1;
        const float4* src = reinterpret_cast<const float4*>(
            g_enc + (size_t)(pbase + pt) * 32 + half * 16);
#pragma unroll
        for (int q = 0; q < 4; q++) {
            const float4 v = src[q];
            const int f = half * 16 + 4 * q;
            st[(f + 0) * STAGE_ST + pt] = v.x;
            st[(f + 1) * STAGE_ST + pt] = v.y;
            st[(f + 2) * STAGE_ST + pt] = v.z;
            st[(f + 3) * STAGE_ST + pt] = v.w;
        }
    }
    __syncwarp();

    // ---- layer-1 A frags (M=16 points, K=32 feats) ----
    unsigned Ahi[4][4], Alo[4][4];
#pragma unroll
    for (int kt = 0; kt < 2; kt++) {
        const int k0 = 2 * lm4 + 16 * kt;
        split_pack(st[k0 * STAGE_ST + l4],           st[(k0 + 1) * STAGE_ST + l4],
                   Ahi[kt][0], Alo[kt][0]);
        split_pack(st[k0 * STAGE_ST + l4 + 8],       st[(k0 + 1) * STAGE_ST + l4 + 8],
                   Ahi[kt][1], Alo[kt][1]);
        split_pack(st[(k0 + 8) * STAGE_ST + l4],     st[(k0 + 9) * STAGE_ST + l4],
                   Ahi[kt][2], Alo[kt][2]);
        split_pack(st[(k0 + 8) * STAGE_ST + l4 + 8], st[(k0 + 9) * STAGE_ST + l4 + 8],
                   Ahi[kt][3], Alo[kt][3]);
    }

    float acc[8][4];
    gemm_layer<2, 8>(acc, Ahi, Alo, s_whi_in,  s_wlo_in,  WSTRIDE_IN, s_bias,       l4, lm4);
    build_frags(acc, Ahi, Alo);
    gemm_layer<4, 8>(acc, Ahi, Alo, s_whi_h0,  s_wlo_h0,  WSTRIDE_H,  s_bias + 64,  l4, lm4);
    build_frags(acc, Ahi, Alo);
    gemm_layer<4, 8>(acc, Ahi, Alo, s_whi_h1,  s_wlo_h1,  WSTRIDE_H,  s_bias + 128, l4, lm4);
    build_frags(acc, Ahi, Alo);
    gemm_layer<4, 2>(acc, Ahi, Alo, s_whi_out, s_wlo_out, WSTRIDE_H,  s_bias + 192, l4, lm4);

    // ---- store output (no activation on final layer) ----
    const int pr = pbase + l4;
#pragma unroll
    for (int nt = 0; nt < 2; nt++) {
        const int j = nt * 8 + 2 * lm4;
        *reinterpret_cast<float2*>(out + (size_t)pr * 16 + j) =
            make_float2(acc[nt][0], acc[nt][1]);
        *reinterpret_cast<float2*>(out + (size_t)(pr + 8) * 16 + j) =
            make_float2(acc[nt][2], acc[nt][3]);
    }
}

extern "C" void kernel_launch(void* const* d_in, const int* in_sizes, int n_in,
                              void* d_out, int out_size) {
    // Identify inputs BY ELEMENT COUNT (robust to metadata ordering).
    const float* coords = nullptr;
    const void*  tables = nullptr;
    const float* w_in = nullptr;  const float* w_h0 = nullptr;
    const float* w_h1 = nullptr;  const float* w_out = nullptr;
    const float* b64[3] = {nullptr, nullptr, nullptr};
    const float* b_out = nullptr;
    int n64 = 0, n4096 = 0;

    for (int i = 0; i < n_in; i++) {
        const int sz = in_sizes[i];
        const void* p = d_in[i];
        switch (sz) {
            case 786432:    coords = (const float*)p; break;     // 262144*3
            case 16777216:  tables = p;               break;     // 16*2^19*2
            case 2048:      w_in   = (const float*)p; break;     // 64*32
            case 1024:      w_out  = (const float*)p; break;     // 16*64
            case 4096:
                if (n4096 == 0) w_h0 = (const float*)p; else w_h1 = (const float*)p;
                n4096++; break;
            case 64:
                if (n64 < 3) b64[n64] = (const float*)p;
                n64++; break;
            case 16:        b_out  = (const float*)p; break;
            default: break;
        }
    }
    const float* b_in = b64[0];
    const float* b_h0 = b64[1];
    const float* b_h1 = b64[2];
    float* out = (float*)d_out;

    static bool attr_set = false;
    if (!attr_set) {
        cudaFuncSetAttribute(mlp_kernel,
                             cudaFuncAttributeMaxDynamicSharedMemorySize,
                             SMEM_TOTAL);
        attr_set = true;
    }

    // Sequential, full-grid launches (R9: chunking starves encode occupancy;
    // R13: LDG weights starve the LSU — weights stay in smem broadcast).
    encode_kernel<<<N_POINTS / ENC_THREADS, ENC_THREADS>>>(coords, tables);
    mlp_kernel<<<N_POINTS / PTS_PER_BLOCK, MLP_THREADS, SMEM_TOTAL>>>(
        w_in, b_in, w_h0, b_h0, w_h1, b_h1, w_out, b_out, out);
}